// round 4
// baseline (speedup 1.0000x reference)
#include <cuda_runtime.h>
#include <cuda_bf16.h>
#include <math.h>
#include <stdint.h>

#define S_LEN 512
#define BATCH 128
#define INPUT 512
#define HID   1024
#define G4    4096            // 4*HID, permuted rows: n' = j*4 + gate
#define KX    1536            // 3*INPUT  augmented K (input projection)
#define KH    3072            // 3*HID    augmented K (recurrent)
#define MX    (S_LEN*BATCH)   // 65536

// ---------------- device scratch (static, no runtime allocation) ----------
__device__ __nv_bfloat16 g_xaug[(size_t)MX * KX];     // [65536][1536] ~201MB
__device__ __nv_bfloat16 g_wih [(size_t)G4 * KX];     // [4096][1536]
__device__ __nv_bfloat16 g_whh [(size_t)G4 * KH];     // [4096][3072]
__device__ float         g_bias[G4];                  // permuted b_ih+b_hh
__device__ float         g_xproj[(size_t)MX * G4];    // [65536][4096] 1GiB
__device__ float         g_c[BATCH * HID];
__device__ float         g_h[BATCH * HID];
__device__ __nv_bfloat16 g_haug[2][BATCH * KH];       // ping-pong [hi|hi|lo]

// ---------------- helpers ----------------
__device__ __forceinline__ uint32_t cvta_s(const void* p) {
    return (uint32_t)__cvta_generic_to_shared(p);
}
__device__ __forceinline__ void ldsm4(uint32_t r[4], uint32_t a) {
    asm volatile("ldmatrix.sync.aligned.m8n8.x4.shared.b16 {%0,%1,%2,%3}, [%4];\n"
                 : "=r"(r[0]), "=r"(r[1]), "=r"(r[2]), "=r"(r[3]) : "r"(a));
}
__device__ __forceinline__ void mma_bf16(float* c, const uint32_t* a,
                                         uint32_t b0, uint32_t b1) {
    asm volatile(
        "mma.sync.aligned.m16n8k16.row.col.f32.bf16.bf16.f32 "
        "{%0,%1,%2,%3},{%4,%5,%6,%7},{%8,%9},{%0,%1,%2,%3};\n"
        : "+f"(c[0]), "+f"(c[1]), "+f"(c[2]), "+f"(c[3])
        : "r"(a[0]), "r"(a[1]), "r"(a[2]), "r"(a[3]), "r"(b0), "r"(b1));
}
__device__ __forceinline__ void cp16(void* s, const void* g) {
    uint32_t sa = cvta_s(s);
    asm volatile("cp.async.cg.shared.global [%0], [%1], 16;\n" :: "r"(sa), "l"(g) : "memory");
}
#define CP_COMMIT() asm volatile("cp.async.commit_group;\n" ::: "memory")
#define CP_WAIT1()  asm volatile("cp.async.wait_group 1;\n" ::: "memory")
#define CP_WAIT0()  asm volatile("cp.async.wait_group 0;\n" ::: "memory")

__device__ __forceinline__ void bf16_split(float v, __nv_bfloat16& hi, __nv_bfloat16& lo) {
    hi = __float2bfloat16(v);
    lo = __float2bfloat16(v - __bfloat162float(hi));
}

// ---------------- prep kernels ----------------
// W_ih [4096,512] row r=g*H+j -> g_wih row n'=j*4+g, cols [hi | lo | hi]
__global__ void prep_wih_kernel(const float* __restrict__ W) {
    int idx = blockIdx.x * 256 + threadIdx.x;
    if (idx >= G4 * INPUT) return;
    int r = idx >> 9, k = idx & 511;
    int g = r >> 10, j = r & 1023;
    int np = j * 4 + g;
    __nv_bfloat16 hi, lo; bf16_split(W[idx], hi, lo);
    size_t base = (size_t)np * KX;
    g_wih[base + k]        = hi;
    g_wih[base + 512 + k]  = lo;
    g_wih[base + 1024 + k] = hi;
}
__global__ void prep_whh_kernel(const float* __restrict__ W) {
    int idx = blockIdx.x * 256 + threadIdx.x;
    if (idx >= G4 * HID) return;
    int r = idx >> 10, k = idx & 1023;
    int g = r >> 10, j = r & 1023;
    int np = j * 4 + g;
    __nv_bfloat16 hi, lo; bf16_split(W[idx], hi, lo);
    size_t base = (size_t)np * KH;
    g_whh[base + k]        = hi;
    g_whh[base + 1024 + k] = lo;
    g_whh[base + 2048 + k] = hi;
}
__global__ void prep_bias_kernel(const float* __restrict__ bih, const float* __restrict__ bhh) {
    int r = blockIdx.x * 256 + threadIdx.x;
    if (r >= G4) return;
    int g = r >> 10, j = r & 1023;
    g_bias[j * 4 + g] = bih[r] + bhh[r];
}
// inputs [65536,512] fp32 -> g_xaug [65536][hi | hi | lo]
__global__ void prep_x_kernel(const float* __restrict__ X) {
    size_t idx = (size_t)blockIdx.x * 256 + threadIdx.x;
    if (idx >= (size_t)MX * INPUT) return;
    int m = (int)(idx >> 9), k = (int)(idx & 511);
    __nv_bfloat16 hi, lo; bf16_split(X[idx], hi, lo);
    size_t base = (size_t)m * KX;
    g_xaug[base + k]        = hi;
    g_xaug[base + 512 + k]  = hi;
    g_xaug[base + 1024 + k] = lo;
}
__global__ void init_state_kernel(const float* __restrict__ h0, const float* __restrict__ c0) {
    int idx = blockIdx.x * 256 + threadIdx.x;
    if (idx >= BATCH * HID) return;
    g_c[idx] = c0[idx];
    __nv_bfloat16 hi, lo; bf16_split(h0[idx], hi, lo);
    int b = idx >> 10, j = idx & 1023;
    size_t base = (size_t)b * KH;
    g_haug[0][base + j]        = hi;
    g_haug[0][base + 1024 + j] = hi;
    g_haug[0][base + 2048 + j] = lo;
}

// ---------------- phase A: x_proj GEMM (M=65536, N=4096, K=1536) -----------
// block tile 128x128, BK=32, 256 threads (8 warps = 4Mx2N), warp tile 32x64
__global__ void __launch_bounds__(256) xproj_kernel() {
    __shared__ __nv_bfloat16 As[2][128 * 40];
    __shared__ __nv_bfloat16 Bs[2][128 * 40];
    const int tid = threadIdx.x, warp = tid >> 5, lane = tid & 31;
    const int nt0 = blockIdx.x * 128, mt0 = blockIdx.y * 128;
    const __nv_bfloat16* Ag = g_xaug + (size_t)mt0 * KX;
    const __nv_bfloat16* Bg = g_wih + (size_t)nt0 * KX;
    const int wm = warp >> 1, wn = warp & 1;

    float c[2][8][4];
#pragma unroll
    for (int i = 0; i < 2; i++)
#pragma unroll
        for (int j = 0; j < 8; j++)
#pragma unroll
            for (int q = 0; q < 4; q++) c[i][j][q] = 0.f;

    auto load = [&](int buf, int k0) {
#pragma unroll
        for (int i = 0; i < 2; i++) {
            int ch = tid + i * 256, row = ch >> 2, kc = (ch & 3) * 8;
            cp16(&As[buf][row * 40 + kc], Ag + (size_t)row * KX + k0 + kc);
        }
#pragma unroll
        for (int i = 0; i < 2; i++) {
            int ch = tid + i * 256, row = ch >> 2, kc = (ch & 3) * 8;
            cp16(&Bs[buf][row * 40 + kc], Bg + (size_t)row * KX + k0 + kc);
        }
    };

    load(0, 0); CP_COMMIT();
    const int NKT = KX / 32;  // 48
    for (int kt = 0; kt < NKT; ++kt) {
        int cur = kt & 1;
        if (kt + 1 < NKT) { load(cur ^ 1, (kt + 1) * 32); CP_COMMIT(); CP_WAIT1(); }
        else CP_WAIT0();
        __syncthreads();
#pragma unroll
        for (int kk = 0; kk < 2; ++kk) {
            int k16 = kk * 16;
            uint32_t a[2][4];
#pragma unroll
            for (int im = 0; im < 2; ++im) {
                int m0 = wm * 32 + im * 16;
                ldsm4(a[im], cvta_s(&As[cur][(m0 + (lane & 15)) * 40 + k16 + ((lane >> 4) << 3)]));
            }
            uint32_t b[4][4];
#pragma unroll
            for (int h = 0; h < 4; ++h) {
                int nrow = wn * 64 + h * 16 + ((lane >> 4) << 3) + (lane & 7);
                int kof = ((lane >> 3) & 1) << 3;
                ldsm4(b[h], cvta_s(&Bs[cur][nrow * 40 + k16 + kof]));
            }
#pragma unroll
            for (int im = 0; im < 2; ++im)
#pragma unroll
                for (int nt = 0; nt < 8; ++nt)
                    mma_bf16(c[im][nt], a[im], b[nt >> 1][(nt & 1) * 2], b[nt >> 1][(nt & 1) * 2 + 1]);
        }
        __syncthreads();
    }
    // epilogue: + bias, write fp32
    int gid = lane >> 2, tg = lane & 3;
#pragma unroll
    for (int im = 0; im < 2; ++im) {
        int rbase = mt0 + wm * 32 + im * 16 + gid;
#pragma unroll
        for (int nt = 0; nt < 8; ++nt) {
            int col = nt0 + wn * 64 + nt * 8 + tg * 2;
            float b0 = __ldg(&g_bias[col]), b1 = __ldg(&g_bias[col + 1]);
            float* o0 = g_xproj + (size_t)rbase * G4 + col;
            o0[0] = c[im][nt][0] + b0; o0[1] = c[im][nt][1] + b1;
            float* o1 = g_xproj + (size_t)(rbase + 8) * G4 + col;
            o1[0] = c[im][nt][2] + b0; o1[1] = c[im][nt][3] + b1;
        }
    }
}

// ---------------- per-step: gates GEMM (128x4096xK3072) + LSTM update ------
// grid 128 blocks (N-tile 32 = 8 hidden units x 4 gates), 256 threads,
// 8 warps each M-tile 16 x N 32. Epilogue fuses activation + c/h update.
__global__ void __launch_bounds__(256) lstm_step_kernel(int src, int dst, int t) {
    __shared__ __nv_bfloat16 As[2][128 * 40];
    __shared__ __nv_bfloat16 Bs[2][32 * 40];
    __shared__ float gates[128 * 33];

    const int tid = threadIdx.x, warp = tid >> 5, lane = tid & 31;
    const int n0 = blockIdx.x * 32;
    const __nv_bfloat16* __restrict__ hsrc = g_haug[src];
    __nv_bfloat16* __restrict__ hdst = g_haug[dst];
    const __nv_bfloat16* Bg = g_whh + (size_t)n0 * KH;

    float c[4][4];
#pragma unroll
    for (int i = 0; i < 4; i++)
#pragma unroll
        for (int j = 0; j < 4; j++) c[i][j] = 0.f;

    auto load = [&](int buf, int k0) {
#pragma unroll
        for (int i = 0; i < 2; i++) {
            int ch = tid + i * 256, row = ch >> 2, kc = (ch & 3) * 8;
            cp16(&As[buf][row * 40 + kc], hsrc + (size_t)row * KH + k0 + kc);
        }
        if (tid < 128) {
            int row = tid >> 2, kc = (tid & 3) * 8;
            cp16(&Bs[buf][row * 40 + kc], Bg + (size_t)row * KH + k0 + kc);
        }
    };

    load(0, 0); CP_COMMIT();
    const int m0 = warp * 16;
    const int NKT = KH / 32;  // 96
    for (int kt = 0; kt < NKT; ++kt) {
        int cur = kt & 1;
        if (kt + 1 < NKT) { load(cur ^ 1, (kt + 1) * 32); CP_COMMIT(); CP_WAIT1(); }
        else CP_WAIT0();
        __syncthreads();
#pragma unroll
        for (int kk = 0; kk < 2; ++kk) {
            int k16 = kk * 16;
            uint32_t a[4];
            ldsm4(a, cvta_s(&As[cur][(m0 + (lane & 15)) * 40 + k16 + ((lane >> 4) << 3)]));
            uint32_t b[2][4];
#pragma unroll
            for (int h = 0; h < 2; ++h) {
                int nrow = h * 16 + ((lane >> 4) << 3) + (lane & 7);
                int kof = ((lane >> 3) & 1) << 3;
                ldsm4(b[h], cvta_s(&Bs[cur][nrow * 40 + k16 + kof]));
            }
#pragma unroll
            for (int nt = 0; nt < 4; ++nt)
                mma_bf16(c[nt], a, b[nt >> 1][(nt & 1) * 2], b[nt >> 1][(nt & 1) * 2 + 1]);
        }
        __syncthreads();
    }

    // stash gate pre-activations (recurrent part) to smem
    int gid = lane >> 2, tg = lane & 3;
#pragma unroll
    for (int nt = 0; nt < 4; ++nt) {
        int col = nt * 8 + tg * 2;
        gates[(m0 + gid) * 33 + col]         = c[nt][0];
        gates[(m0 + gid) * 33 + col + 1]     = c[nt][1];
        gates[(m0 + gid + 8) * 33 + col]     = c[nt][2];
        gates[(m0 + gid + 8) * 33 + col + 1] = c[nt][3];
    }
    __syncthreads();

    // fused LSTM cell update: 1024 (batch, hidden) pairs, 4 per thread
    const float* xp = g_xproj + (size_t)t * BATCH * G4;
#pragma unroll
    for (int i = 0; i < 4; ++i) {
        int p = tid + i * 256;          // 0..1023
        int b = p >> 3, jj = p & 7;
        int j = blockIdx.x * 8 + jj;
        float4 xv = *(const float4*)(xp + (size_t)b * G4 + n0 + jj * 4);
        float ig = gates[b * 33 + jj * 4 + 0] + xv.x;
        float fg = gates[b * 33 + jj * 4 + 1] + xv.y;
        float gg = gates[b * 33 + jj * 4 + 2] + xv.z;
        float og = gates[b * 33 + jj * 4 + 3] + xv.w;
        float ia = 1.f / (1.f + expf(-ig));
        float fa = 1.f / (1.f + expf(-fg));
        float ga = tanhf(gg);
        float oa = 1.f / (1.f + expf(-og));
        float cn = fa * g_c[b * HID + j] + ia * ga;
        float hn = oa * tanhf(cn);
        g_c[b * HID + j] = cn;
        g_h[b * HID + j] = hn;
        __nv_bfloat16 hi, lo; bf16_split(hn, hi, lo);
        size_t base = (size_t)b * KH;
        hdst[base + j]        = hi;
        hdst[base + 1024 + j] = hi;
        hdst[base + 2048 + j] = lo;
    }
}

// ---------------- decoder + softmax over batch dim -------------------------
__global__ void decoder_kernel(const float* __restrict__ Wdec,
                               const float* __restrict__ bdec,
                               float* __restrict__ out) {
    __shared__ float sl[512];
    __shared__ float red[8];
    int tid = threadIdx.x;
    int b = tid >> 2, o = tid & 3;
    const float4* h4 = (const float4*)(g_h + b * HID);
    const float4* w4 = (const float4*)(Wdec + o * HID);
    float acc = bdec[o];
    for (int k = 0; k < HID / 4; ++k) {
        float4 hv = h4[k], wv = w4[k];
        acc += hv.x * wv.x + hv.y * wv.y + hv.z * wv.z + hv.w * wv.w;
    }
    sl[tid] = acc;
    __syncthreads();
    if (tid < 4) {
        float mx = -1e30f;
        for (int bb = 0; bb < 128; ++bb) mx = fmaxf(mx, sl[bb * 4 + tid]);
        float s = 0.f;
        for (int bb = 0; bb < 128; ++bb) s += expf(sl[bb * 4 + tid] - mx);
        red[tid] = mx; red[4 + tid] = s;
    }
    __syncthreads();
    out[tid] = expf(sl[tid] - red[o]) / red[4 + o];
}

// ---------------- launch ----------------
extern "C" void kernel_launch(void* const* d_in, const int* in_sizes, int n_in,
                              void* d_out, int out_size) {
    const float* inputs = (const float*)d_in[0];
    const float* h0     = (const float*)d_in[1];
    const float* c0     = (const float*)d_in[2];
    const float* Wih    = (const float*)d_in[3];
    const float* Whh    = (const float*)d_in[4];
    const float* bih    = (const float*)d_in[5];
    const float* bhh    = (const float*)d_in[6];
    const float* Wdec   = (const float*)d_in[7];
    const float* bdec   = (const float*)d_in[8];
    float* out = (float*)d_out;

    prep_wih_kernel<<<(G4 * INPUT + 255) / 256, 256>>>(Wih);
    prep_whh_kernel<<<(G4 * HID + 255) / 256, 256>>>(Whh);
    prep_bias_kernel<<<(G4 + 255) / 256, 256>>>(bih, bhh);
    prep_x_kernel<<<(int)(((size_t)MX * INPUT + 255) / 256), 256>>>(inputs);
    init_state_kernel<<<(BATCH * HID + 255) / 256, 256>>>(h0, c0);

    xproj_kernel<<<dim3(G4 / 128, MX / 128), 256>>>();

    for (int t = 0; t < S_LEN; ++t)
        lstm_step_kernel<<<128, 256>>>(t & 1, (t + 1) & 1, t);

    decoder_kernel<<<1, 512>>>(Wdec, bdec, out);
}

// round 5
// speedup vs baseline: 2.1588x; 2.1588x over previous
#include <cuda_runtime.h>
#include <cuda_bf16.h>
#include <math.h>
#include <stdint.h>

#define S_LEN 512
#define BATCH 128
#define INPUT 512
#define HID   1024
#define G4    4096            // 4*HID, permuted rows: n' = j*4 + gate
#define MX    (S_LEN*BATCH)   // 65536

// Strip geometry: K-strips of 32 bf16, stored padded to pitch 40 (80B rows,
// conflict-free for ldmatrix). A-strip = 128 rows x 40 = 5120 elems (10240B).
// B-strip (step) = 32 rows x 40 = 1280 elems (2560B).
#define ASTRIP 5120
#define BSTRIP 1280

// ---------------- device scratch (static, no runtime allocation) ----------
// xproj operands: [mt 512][strip 32 (hi 0-15 | lo 16-31)][128][40]
__device__ __nv_bfloat16 g_xaug2[(size_t)512 * 32 * ASTRIP];   // ~168MB
// W_ih: [nt 32][strip 32 (whi | wlo)][128][40]
__device__ __nv_bfloat16 g_wih2[(size_t)32 * 32 * ASTRIP];     // ~10.5MB
// W_hh: [nb 128][strip 64 (whi 0-31 | wlo 32-63)][32][40]
__device__ __nv_bfloat16 g_whh2[(size_t)128 * 64 * BSTRIP];    // ~21MB
__device__ float         g_bias[G4];                            // permuted b_ih+b_hh
__device__ float         g_xproj[(size_t)MX * G4];              // 1GiB fp32
__device__ float         g_c[BATCH * HID];
__device__ float         g_h[BATCH * HID];
// recurrent h: [strip 64 (hi 0-31 | lo 32-63)][128 b][40], ping-pong
__device__ __nv_bfloat16 g_haug2[2][64 * ASTRIP];

// ---------------- helpers ----------------
__device__ __forceinline__ uint32_t cvta_s(const void* p) {
    return (uint32_t)__cvta_generic_to_shared(p);
}
__device__ __forceinline__ void ldsm4(uint32_t r[4], uint32_t a) {
    asm volatile("ldmatrix.sync.aligned.m8n8.x4.shared.b16 {%0,%1,%2,%3}, [%4];\n"
                 : "=r"(r[0]), "=r"(r[1]), "=r"(r[2]), "=r"(r[3]) : "r"(a));
}
__device__ __forceinline__ void mma_bf16(float* c, const uint32_t* a,
                                         uint32_t b0, uint32_t b1) {
    asm volatile(
        "mma.sync.aligned.m16n8k16.row.col.f32.bf16.bf16.f32 "
        "{%0,%1,%2,%3},{%4,%5,%6,%7},{%8,%9},{%0,%1,%2,%3};\n"
        : "+f"(c[0]), "+f"(c[1]), "+f"(c[2]), "+f"(c[3])
        : "r"(a[0]), "r"(a[1]), "r"(a[2]), "r"(a[3]), "r"(b0), "r"(b1));
}
__device__ __forceinline__ void mbar_init(void* m, uint32_t cnt) {
    asm volatile("mbarrier.init.shared.b64 [%0], %1;\n"
                 :: "r"(cvta_s(m)), "r"(cnt) : "memory");
}
__device__ __forceinline__ void mbar_expect(uint32_t mb, uint32_t bytes) {
    asm volatile("mbarrier.arrive.expect_tx.shared.b64 _, [%0], %1;\n"
                 :: "r"(mb), "r"(bytes) : "memory");
}
__device__ __forceinline__ void bulk_g2s(void* dst, const void* src,
                                         uint32_t bytes, uint32_t mb) {
    asm volatile("cp.async.bulk.shared::cta.global.mbarrier::complete_tx::bytes "
                 "[%0], [%1], %2, [%3];\n"
                 :: "r"(cvta_s(dst)), "l"(src), "r"(bytes), "r"(mb) : "memory");
}
__device__ __forceinline__ void mbar_wait(void* m, uint32_t parity) {
    uint32_t a = cvta_s(m);
    asm volatile(
        "{\n.reg .pred P;\n"
        "W_%=:\n"
        "mbarrier.try_wait.parity.shared.b64 P, [%0], %1;\n"
        "@!P bra W_%=;\n}\n"
        :: "r"(a), "r"(parity) : "memory");
}
__device__ __forceinline__ void bf16_split(float v, __nv_bfloat16& hi, __nv_bfloat16& lo) {
    hi = __float2bfloat16(v);
    lo = __float2bfloat16(v - __bfloat162float(hi));
}

// ---------------- prep kernels ----------------
// inputs [65536,512] fp32 -> g_xaug2 strips (hi | lo)
__global__ void prep_x_kernel(const float* __restrict__ X) {
    size_t idx = (size_t)blockIdx.x * 256 + threadIdx.x;
    if (idx >= (size_t)MX * INPUT) return;
    int m = (int)(idx >> 9), k = (int)(idx & 511);
    int mt = m >> 7, mr = m & 127;
    int s = k >> 5, kc = k & 31;
    __nv_bfloat16 hi, lo; bf16_split(X[idx], hi, lo);
    size_t base = (size_t)mt * (32 * ASTRIP) + (size_t)mr * 40 + kc;
    g_xaug2[base + (size_t)s * ASTRIP]        = hi;
    g_xaug2[base + (size_t)(16 + s) * ASTRIP] = lo;
}
// W_ih [4096,512]: row r = g*H+j -> n' = j*4+g
__global__ void prep_wih_kernel(const float* __restrict__ W) {
    int idx = blockIdx.x * 256 + threadIdx.x;
    if (idx >= G4 * INPUT) return;
    int r = idx >> 9, k = idx & 511;
    int g = r >> 10, j = r & 1023;
    int np = j * 4 + g;
    int nt = np >> 7, nr = np & 127;
    int s = k >> 5, kc = k & 31;
    __nv_bfloat16 hi, lo; bf16_split(W[idx], hi, lo);
    size_t base = (size_t)nt * (32 * ASTRIP) + (size_t)nr * 40 + kc;
    g_wih2[base + (size_t)s * ASTRIP]        = hi;
    g_wih2[base + (size_t)(16 + s) * ASTRIP] = lo;
}
// W_hh [4096,1024]
__global__ void prep_whh_kernel(const float* __restrict__ W) {
    int idx = blockIdx.x * 256 + threadIdx.x;
    if (idx >= G4 * HID) return;
    int r = idx >> 10, k = idx & 1023;
    int g = r >> 10, j = r & 1023;
    int np = j * 4 + g;
    int nb = np >> 5, nr = np & 31;
    int s = k >> 5, kc = k & 31;
    __nv_bfloat16 hi, lo; bf16_split(W[idx], hi, lo);
    size_t base = (size_t)nb * (64 * BSTRIP) + (size_t)nr * 40 + kc;
    g_whh2[base + (size_t)s * BSTRIP]        = hi;
    g_whh2[base + (size_t)(32 + s) * BSTRIP] = lo;
}
__global__ void prep_bias_kernel(const float* __restrict__ bih, const float* __restrict__ bhh) {
    int r = blockIdx.x * 256 + threadIdx.x;
    if (r >= G4) return;
    int g = r >> 10, j = r & 1023;
    g_bias[j * 4 + g] = bih[r] + bhh[r];
}
__global__ void init_state_kernel(const float* __restrict__ h0, const float* __restrict__ c0) {
    int idx = blockIdx.x * 256 + threadIdx.x;
    if (idx >= BATCH * HID) return;
    g_c[idx] = c0[idx];
    int b = idx >> 10, j = idx & 1023;
    __nv_bfloat16 hi, lo; bf16_split(h0[idx], hi, lo);
    int s = j >> 5, kc = j & 31;
    g_haug2[0][(size_t)s * ASTRIP + b * 40 + kc]        = hi;
    g_haug2[0][(size_t)(32 + s) * ASTRIP + b * 40 + kc] = lo;
}

// ---------------- phase A: x_proj GEMM (M=65536, N=4096, Kunique=1024) -----
// block 128x128, 256 threads (8 warps 4Mx2N, warp 32x64), 16 strip stages.
// Per stage: A_hi, A_lo, B_whi, B_wlo resident; products hi*whi + hi*wlo + lo*whi.
__global__ void __launch_bounds__(256) xproj_kernel() {
    extern __shared__ char dyn[];
    __nv_bfloat16* sm = (__nv_bfloat16*)dyn;            // [2][4][5120]
    uint64_t* mbar = (uint64_t*)(dyn + 81920);

    const int tid = threadIdx.x, warp = tid >> 5, lane = tid & 31;
    const int nt0 = blockIdx.x * 128, mt0 = blockIdx.y * 128;
    const __nv_bfloat16* Ab = g_xaug2 + (size_t)blockIdx.y * (32 * ASTRIP);
    const __nv_bfloat16* Bb = g_wih2 + (size_t)blockIdx.x * (32 * ASTRIP);
    const int wm = warp >> 1, wn = warp & 1;

    if (tid == 0) { mbar_init(&mbar[0], 1); mbar_init(&mbar[1], 1); }
    __syncthreads();

    float c[2][8][4];
#pragma unroll
    for (int i = 0; i < 2; i++)
#pragma unroll
        for (int j = 0; j < 8; j++)
#pragma unroll
            for (int q = 0; q < 4; q++) c[i][j][q] = 0.f;

    auto issue = [&](int s, int buf) {
        uint32_t mb = cvta_s(&mbar[buf]);
        mbar_expect(mb, 4 * 10240);
        __nv_bfloat16* d = sm + buf * (4 * ASTRIP);
        bulk_g2s(d,              Ab + (size_t)s * ASTRIP,        10240, mb);
        bulk_g2s(d + ASTRIP,     Ab + (size_t)(16 + s) * ASTRIP, 10240, mb);
        bulk_g2s(d + 2 * ASTRIP, Bb + (size_t)s * ASTRIP,        10240, mb);
        bulk_g2s(d + 3 * ASTRIP, Bb + (size_t)(16 + s) * ASTRIP, 10240, mb);
    };

    if (tid == 0) issue(0, 0);
    for (int s = 0; s < 16; ++s) {
        int buf = s & 1, par = (s >> 1) & 1;
        if (tid == 0 && s + 1 < 16) issue(s + 1, buf ^ 1);
        mbar_wait(&mbar[buf], par);
        const __nv_bfloat16* A0 = sm + buf * (4 * ASTRIP);
        const __nv_bfloat16* A1 = A0 + ASTRIP;
        const __nv_bfloat16* B0 = A0 + 2 * ASTRIP;
        const __nv_bfloat16* B1 = A0 + 3 * ASTRIP;
#pragma unroll
        for (int kk = 0; kk < 2; ++kk) {
            int k16 = kk * 16;
            uint32_t ah[2][4], al[2][4];
#pragma unroll
            for (int im = 0; im < 2; ++im) {
                int aoff = (wm * 32 + im * 16 + (lane & 15)) * 40 + k16 + ((lane >> 4) << 3);
                ldsm4(ah[im], cvta_s(A0 + aoff));
                ldsm4(al[im], cvta_s(A1 + aoff));
            }
            uint32_t bh[4][4], bl[4][4];
#pragma unroll
            for (int h = 0; h < 4; ++h) {
                int boff = (wn * 64 + h * 16 + ((lane >> 4) << 3) + (lane & 7)) * 40
                           + k16 + (((lane >> 3) & 1) << 3);
                ldsm4(bh[h], cvta_s(B0 + boff));
                ldsm4(bl[h], cvta_s(B1 + boff));
            }
#pragma unroll
            for (int im = 0; im < 2; ++im)
#pragma unroll
                for (int nt = 0; nt < 8; ++nt) {
                    uint32_t h0r = bh[nt >> 1][(nt & 1) * 2], h1r = bh[nt >> 1][(nt & 1) * 2 + 1];
                    uint32_t l0r = bl[nt >> 1][(nt & 1) * 2], l1r = bl[nt >> 1][(nt & 1) * 2 + 1];
                    mma_bf16(c[im][nt], ah[im], h0r, h1r);   // hi * whi
                    mma_bf16(c[im][nt], ah[im], l0r, l1r);   // hi * wlo
                    mma_bf16(c[im][nt], al[im], h0r, h1r);   // lo * whi
                }
        }
        __syncthreads();
    }
    // epilogue: + bias, write fp32
    int gid = lane >> 2, tg = lane & 3;
#pragma unroll
    for (int im = 0; im < 2; ++im) {
        int rbase = mt0 + wm * 32 + im * 16 + gid;
#pragma unroll
        for (int nt = 0; nt < 8; ++nt) {
            int col = nt0 + wn * 64 + nt * 8 + tg * 2;
            float b0 = __ldg(&g_bias[col]), b1 = __ldg(&g_bias[col + 1]);
            float* o0 = g_xproj + (size_t)rbase * G4 + col;
            o0[0] = c[im][nt][0] + b0; o0[1] = c[im][nt][1] + b1;
            float* o1 = g_xproj + (size_t)(rbase + 8) * G4 + col;
            o1[0] = c[im][nt][2] + b0; o1[1] = c[im][nt][3] + b1;
        }
    }
}

// ---------------- per-step: gates GEMM + fused LSTM update -----------------
// 128 blocks (N-tile 32 = 8 hidden x 4 gates), 256 threads, warp = M16 tile.
// 32 strip stages; per stage A_hi/A_lo (10KB each) + B_whi/B_wlo (2.5KB each).
__global__ void __launch_bounds__(256) lstm_step_kernel(int src, int dst, int t) {
    extern __shared__ char dyn[];
    __nv_bfloat16* smA = (__nv_bfloat16*)dyn;             // [2][2][5120]
    __nv_bfloat16* smB = (__nv_bfloat16*)(dyn + 40960);   // [2][2][1280]
    float* gates = (float*)(dyn + 51200);                 // 128*33
    uint64_t* mbar = (uint64_t*)(dyn + 68096);

    const int tid = threadIdx.x, warp = tid >> 5, lane = tid & 31;
    const int nb = blockIdx.x, n0 = nb * 32;
    const __nv_bfloat16* __restrict__ Ab = g_haug2[src];
    __nv_bfloat16* __restrict__ hdst = g_haug2[dst];
    const __nv_bfloat16* Bb = g_whh2 + (size_t)nb * (64 * BSTRIP);

    if (tid == 0) { mbar_init(&mbar[0], 1); mbar_init(&mbar[1], 1); }
    __syncthreads();

    float c[4][4];
#pragma unroll
    for (int i = 0; i < 4; i++)
#pragma unroll
        for (int j = 0; j < 4; j++) c[i][j] = 0.f;

    auto issue = [&](int s, int buf) {
        uint32_t mb = cvta_s(&mbar[buf]);
        mbar_expect(mb, 2 * 10240 + 2 * 2560);
        __nv_bfloat16* dA = smA + buf * (2 * ASTRIP);
        __nv_bfloat16* dB = smB + buf * (2 * BSTRIP);
        bulk_g2s(dA,          Ab + (size_t)s * ASTRIP,        10240, mb);
        bulk_g2s(dA + ASTRIP, Ab + (size_t)(32 + s) * ASTRIP, 10240, mb);
        bulk_g2s(dB,          Bb + (size_t)s * BSTRIP,        2560,  mb);
        bulk_g2s(dB + BSTRIP, Bb + (size_t)(32 + s) * BSTRIP, 2560,  mb);
    };

    if (tid == 0) issue(0, 0);
    const int m0 = warp * 16;
    for (int s = 0; s < 32; ++s) {
        int buf = s & 1, par = (s >> 1) & 1;
        if (tid == 0 && s + 1 < 32) issue(s + 1, buf ^ 1);
        mbar_wait(&mbar[buf], par);
        const __nv_bfloat16* A0 = smA + buf * (2 * ASTRIP);
        const __nv_bfloat16* A1 = A0 + ASTRIP;
        const __nv_bfloat16* B0 = smB + buf * (2 * BSTRIP);
        const __nv_bfloat16* B1 = B0 + BSTRIP;
#pragma unroll
        for (int kk = 0; kk < 2; ++kk) {
            int k16 = kk * 16;
            int aoff = (m0 + (lane & 15)) * 40 + k16 + ((lane >> 4) << 3);
            uint32_t ah[4], al[4];
            ldsm4(ah, cvta_s(A0 + aoff));
            ldsm4(al, cvta_s(A1 + aoff));
            uint32_t bh[2][4], bl[2][4];
#pragma unroll
            for (int h = 0; h < 2; ++h) {
                int boff = (h * 16 + ((lane >> 4) << 3) + (lane & 7)) * 40
                           + k16 + (((lane >> 3) & 1) << 3);
                ldsm4(bh[h], cvta_s(B0 + boff));
                ldsm4(bl[h], cvta_s(B1 + boff));
            }
#pragma unroll
            for (int nt = 0; nt < 4; ++nt) {
                uint32_t h0r = bh[nt >> 1][(nt & 1) * 2], h1r = bh[nt >> 1][(nt & 1) * 2 + 1];
                uint32_t l0r = bl[nt >> 1][(nt & 1) * 2], l1r = bl[nt >> 1][(nt & 1) * 2 + 1];
                mma_bf16(c[nt], ah, h0r, h1r);   // hi * whi
                mma_bf16(c[nt], ah, l0r, l1r);   // hi * wlo
                mma_bf16(c[nt], al, h0r, h1r);   // lo * whi
            }
        }
        __syncthreads();
    }

    // stash recurrent gate pre-activations to smem
    int gid = lane >> 2, tg = lane & 3;
#pragma unroll
    for (int nt = 0; nt < 4; ++nt) {
        int col = nt * 8 + tg * 2;
        gates[(m0 + gid) * 33 + col]         = c[nt][0];
        gates[(m0 + gid) * 33 + col + 1]     = c[nt][1];
        gates[(m0 + gid + 8) * 33 + col]     = c[nt][2];
        gates[(m0 + gid + 8) * 33 + col + 1] = c[nt][3];
    }
    __syncthreads();

    // fused LSTM cell update: 1024 (batch, hidden) pairs, 4 per thread
    const float* xp = g_xproj + (size_t)t * BATCH * G4;
#pragma unroll
    for (int i = 0; i < 4; ++i) {
        int p = tid + i * 256;          // 0..1023
        int b = p >> 3, jj = p & 7;
        int j = nb * 8 + jj;
        float4 xv = *(const float4*)(xp + (size_t)b * G4 + n0 + jj * 4);
        float ig = gates[b * 33 + jj * 4 + 0] + xv.x;
        float fg = gates[b * 33 + jj * 4 + 1] + xv.y;
        float gg = gates[b * 33 + jj * 4 + 2] + xv.z;
        float og = gates[b * 33 + jj * 4 + 3] + xv.w;
        float ia = 1.f / (1.f + expf(-ig));
        float fa = 1.f / (1.f + expf(-fg));
        float ga = tanhf(gg);
        float oa = 1.f / (1.f + expf(-og));
        float cn = fa * g_c[b * HID + j] + ia * ga;
        float hn = oa * tanhf(cn);
        g_c[b * HID + j] = cn;
        g_h[b * HID + j] = hn;
        __nv_bfloat16 hi, lo; bf16_split(hn, hi, lo);
        int sA = j >> 5, kc = j & 31;
        hdst[(size_t)sA * ASTRIP + b * 40 + kc]        = hi;
        hdst[(size_t)(32 + sA) * ASTRIP + b * 40 + kc] = lo;
    }
}

// ---------------- decoder + softmax over batch dim -------------------------
__global__ void decoder_kernel(const float* __restrict__ Wdec,
                               const float* __restrict__ bdec,
                               float* __restrict__ out) {
    __shared__ float sl[512];
    __shared__ float red[8];
    int tid = threadIdx.x;
    int b = tid >> 2, o = tid & 3;
    const float4* h4 = (const float4*)(g_h + b * HID);
    const float4* w4 = (const float4*)(Wdec + o * HID);
    float acc = bdec[o];
    for (int k = 0; k < HID / 4; ++k) {
        float4 hv = h4[k], wv = w4[k];
        acc += hv.x * wv.x + hv.y * wv.y + hv.z * wv.z + hv.w * wv.w;
    }
    sl[tid] = acc;
    __syncthreads();
    if (tid < 4) {
        float mx = -1e30f;
        for (int bb = 0; bb < 128; ++bb) mx = fmaxf(mx, sl[bb * 4 + tid]);
        float s = 0.f;
        for (int bb = 0; bb < 128; ++bb) s += expf(sl[bb * 4 + tid] - mx);
        red[tid] = mx; red[4 + tid] = s;
    }
    __syncthreads();
    out[tid] = expf(sl[tid] - red[o]) / red[4 + o];
}

// ---------------- launch ----------------
extern "C" void kernel_launch(void* const* d_in, const int* in_sizes, int n_in,
                              void* d_out, int out_size) {
    const float* inputs = (const float*)d_in[0];
    const float* h0     = (const float*)d_in[1];
    const float* c0     = (const float*)d_in[2];
    const float* Wih    = (const float*)d_in[3];
    const float* Whh    = (const float*)d_in[4];
    const float* bih    = (const float*)d_in[5];
    const float* bhh    = (const float*)d_in[6];
    const float* Wdec   = (const float*)d_in[7];
    const float* bdec   = (const float*)d_in[8];
    float* out = (float*)d_out;

    const int XPROJ_SMEM = 81920 + 32;   // 2 bufs x 4 strips x 10240B + mbar
    const int STEP_SMEM  = 68112;        // A 40960 + B 10240 + gates 16896 + mbar
    cudaFuncSetAttribute(xproj_kernel, cudaFuncAttributeMaxDynamicSharedMemorySize, XPROJ_SMEM);
    cudaFuncSetAttribute(lstm_step_kernel, cudaFuncAttributeMaxDynamicSharedMemorySize, STEP_SMEM);

    prep_wih_kernel<<<(G4 * INPUT + 255) / 256, 256>>>(Wih);
    prep_whh_kernel<<<(G4 * HID + 255) / 256, 256>>>(Whh);
    prep_bias_kernel<<<(G4 + 255) / 256, 256>>>(bih, bhh);
    prep_x_kernel<<<(int)(((size_t)MX * INPUT + 255) / 256), 256>>>(inputs);
    init_state_kernel<<<(BATCH * HID + 255) / 256, 256>>>(h0, c0);

    xproj_kernel<<<dim3(G4 / 128, MX / 128), 256, XPROJ_SMEM>>>();

    for (int t = 0; t < S_LEN; ++t)
        lstm_step_kernel<<<128, 256, STEP_SMEM>>>(t & 1, (t + 1) & 1, t);

    decoder_kernel<<<1, 512>>>(Wdec, bdec, out);
}

// round 6
// speedup vs baseline: 2.5809x; 1.1955x over previous
#include <cuda_runtime.h>
#include <cuda_bf16.h>
#include <math.h>
#include <stdint.h>

#define S_LEN 512
#define BATCH 128
#define INPUT 512
#define HID   1024
#define G4    4096            // 4*HID, permuted rows: n' = j*4 + gate
#define MX    (S_LEN*BATCH)   // 65536
#define NBLK  128

// Strip geometry: K-strips of 32 bf16, padded pitch 40 (80B rows, conflict-free
// ldmatrix). A-strip = 128 rows x 40 = 5120 elems (10240B). B-strip = 32 x 40.
#define ASTRIP 5120
#define BSTRIP 1280

// ---------------- device scratch (static, no runtime allocation) ----------
__device__ __nv_bfloat16 g_xaug2[(size_t)512 * 32 * ASTRIP];   // ~168MB
__device__ __nv_bfloat16 g_wih2[(size_t)32 * 32 * ASTRIP];     // ~10.5MB
__device__ __nv_bfloat16 g_whh2[(size_t)128 * 64 * BSTRIP];    // ~21MB
__device__ float         g_bias[G4];
// x_proj, blocked for step prefetch: [t 512][nb 128][b 128][32] fp32 (1GiB)
__device__ float         g_xproj[(size_t)S_LEN * NBLK * BATCH * 32];
__device__ float         g_c[BATCH * HID];
__device__ float         g_h[BATCH * HID];
// recurrent h: [strip 64 (hi 0-31 | lo 32-63)][128 b][40], ping-pong
__device__ __nv_bfloat16 g_haug2[2][64 * ASTRIP];
// grid barrier state
__device__ unsigned g_cnt;
__device__ volatile unsigned g_gen;

// ---------------- helpers ----------------
__device__ __forceinline__ uint32_t cvta_s(const void* p) {
    return (uint32_t)__cvta_generic_to_shared(p);
}
__device__ __forceinline__ void ldsm4(uint32_t r[4], uint32_t a) {
    asm volatile("ldmatrix.sync.aligned.m8n8.x4.shared.b16 {%0,%1,%2,%3}, [%4];\n"
                 : "=r"(r[0]), "=r"(r[1]), "=r"(r[2]), "=r"(r[3]) : "r"(a));
}
__device__ __forceinline__ void mma_bf16(float* c, const uint32_t* a,
                                         uint32_t b0, uint32_t b1) {
    asm volatile(
        "mma.sync.aligned.m16n8k16.row.col.f32.bf16.bf16.f32 "
        "{%0,%1,%2,%3},{%4,%5,%6,%7},{%8,%9},{%0,%1,%2,%3};\n"
        : "+f"(c[0]), "+f"(c[1]), "+f"(c[2]), "+f"(c[3])
        : "r"(a[0]), "r"(a[1]), "r"(a[2]), "r"(a[3]), "r"(b0), "r"(b1));
}
__device__ __forceinline__ void mbar_init(void* m, uint32_t cnt) {
    asm volatile("mbarrier.init.shared.b64 [%0], %1;\n"
                 :: "r"(cvta_s(m)), "r"(cnt) : "memory");
}
__device__ __forceinline__ void mbar_expect(uint32_t mb, uint32_t bytes) {
    asm volatile("mbarrier.arrive.expect_tx.shared.b64 _, [%0], %1;\n"
                 :: "r"(mb), "r"(bytes) : "memory");
}
__device__ __forceinline__ void bulk_g2s(void* dst, const void* src,
                                         uint32_t bytes, uint32_t mb) {
    asm volatile("cp.async.bulk.shared::cta.global.mbarrier::complete_tx::bytes "
                 "[%0], [%1], %2, [%3];\n"
                 :: "r"(cvta_s(dst)), "l"(src), "r"(bytes), "r"(mb) : "memory");
}
__device__ __forceinline__ void mbar_wait(void* m, uint32_t parity) {
    uint32_t a = cvta_s(m);
    asm volatile(
        "{\n.reg .pred P;\n"
        "W_%=:\n"
        "mbarrier.try_wait.parity.shared.b64 P, [%0], %1;\n"
        "@!P bra W_%=;\n}\n"
        :: "r"(a), "r"(parity) : "memory");
}
__device__ __forceinline__ void bf16_split(float v, __nv_bfloat16& hi, __nv_bfloat16& lo) {
    hi = __float2bfloat16(v);
    lo = __float2bfloat16(v - __bfloat162float(hi));
}
__device__ __forceinline__ void grid_barrier() {
    __threadfence();
    __syncthreads();
    if (threadIdx.x == 0) {
        unsigned gen = g_gen;
        if (atomicAdd(&g_cnt, 1u) == NBLK - 1u) {
            *((volatile unsigned*)&g_cnt) = 0u;
            __threadfence();
            g_gen = gen + 1u;
        } else {
            while (g_gen == gen) __nanosleep(32);
        }
    }
    __syncthreads();
    __threadfence();
}

// ---------------- prep kernels ----------------
__global__ void prep_x_kernel(const float* __restrict__ X) {
    size_t idx = (size_t)blockIdx.x * 256 + threadIdx.x;
    if (idx >= (size_t)MX * INPUT) return;
    int m = (int)(idx >> 9), k = (int)(idx & 511);
    int mt = m >> 7, mr = m & 127;
    int s = k >> 5, kc = k & 31;
    __nv_bfloat16 hi, lo; bf16_split(X[idx], hi, lo);
    size_t base = (size_t)mt * (32 * ASTRIP) + (size_t)mr * 40 + kc;
    g_xaug2[base + (size_t)s * ASTRIP]        = hi;
    g_xaug2[base + (size_t)(16 + s) * ASTRIP] = lo;
}
__global__ void prep_wih_kernel(const float* __restrict__ W) {
    int idx = blockIdx.x * 256 + threadIdx.x;
    if (idx >= G4 * INPUT) return;
    int r = idx >> 9, k = idx & 511;
    int g = r >> 10, j = r & 1023;
    int np = j * 4 + g;
    int nt = np >> 7, nr = np & 127;
    int s = k >> 5, kc = k & 31;
    __nv_bfloat16 hi, lo; bf16_split(W[idx], hi, lo);
    size_t base = (size_t)nt * (32 * ASTRIP) + (size_t)nr * 40 + kc;
    g_wih2[base + (size_t)s * ASTRIP]        = hi;
    g_wih2[base + (size_t)(16 + s) * ASTRIP] = lo;
}
__global__ void prep_whh_kernel(const float* __restrict__ W) {
    int idx = blockIdx.x * 256 + threadIdx.x;
    if (idx >= G4 * HID) return;
    int r = idx >> 10, k = idx & 1023;
    int g = r >> 10, j = r & 1023;
    int np = j * 4 + g;
    int nb = np >> 5, nr = np & 31;
    int s = k >> 5, kc = k & 31;
    __nv_bfloat16 hi, lo; bf16_split(W[idx], hi, lo);
    size_t base = (size_t)nb * (64 * BSTRIP) + (size_t)nr * 40 + kc;
    g_whh2[base + (size_t)s * BSTRIP]        = hi;
    g_whh2[base + (size_t)(32 + s) * BSTRIP] = lo;
}
__global__ void prep_bias_kernel(const float* __restrict__ bih, const float* __restrict__ bhh) {
    int r = blockIdx.x * 256 + threadIdx.x;
    if (r >= G4) return;
    int g = r >> 10, j = r & 1023;
    g_bias[j * 4 + g] = bih[r] + bhh[r];
}
__global__ void init_state_kernel(const float* __restrict__ h0, const float* __restrict__ c0) {
    int idx = blockIdx.x * 256 + threadIdx.x;
    if (idx >= BATCH * HID) return;
    g_c[idx] = c0[idx];
    int b = idx >> 10, j = idx & 1023;
    __nv_bfloat16 hi, lo; bf16_split(h0[idx], hi, lo);
    int s = j >> 5, kc = j & 31;
    g_haug2[0][(size_t)s * ASTRIP + b * 40 + kc]        = hi;
    g_haug2[0][(size_t)(32 + s) * ASTRIP + b * 40 + kc] = lo;
}

// ---------------- phase A: x_proj GEMM (M=65536, N=4096, Kuniq=1024) -------
__global__ void __launch_bounds__(256) xproj_kernel() {
    extern __shared__ char dyn[];
    __nv_bfloat16* sm = (__nv_bfloat16*)dyn;            // [2][4][5120]
    uint64_t* mbar = (uint64_t*)(dyn + 81920);

    const int tid = threadIdx.x, warp = tid >> 5, lane = tid & 31;
    const int nt0 = blockIdx.x * 128, mt0 = blockIdx.y * 128;
    const __nv_bfloat16* Ab = g_xaug2 + (size_t)blockIdx.y * (32 * ASTRIP);
    const __nv_bfloat16* Bb = g_wih2 + (size_t)blockIdx.x * (32 * ASTRIP);
    const int wm = warp >> 1, wn = warp & 1;

    if (tid == 0) { mbar_init(&mbar[0], 1); mbar_init(&mbar[1], 1); }
    __syncthreads();

    float c[2][8][4];
#pragma unroll
    for (int i = 0; i < 2; i++)
#pragma unroll
        for (int j = 0; j < 8; j++)
#pragma unroll
            for (int q = 0; q < 4; q++) c[i][j][q] = 0.f;

    auto issue = [&](int s, int buf) {
        uint32_t mb = cvta_s(&mbar[buf]);
        mbar_expect(mb, 4 * 10240);
        __nv_bfloat16* d = sm + buf * (4 * ASTRIP);
        bulk_g2s(d,              Ab + (size_t)s * ASTRIP,        10240, mb);
        bulk_g2s(d + ASTRIP,     Ab + (size_t)(16 + s) * ASTRIP, 10240, mb);
        bulk_g2s(d + 2 * ASTRIP, Bb + (size_t)s * ASTRIP,        10240, mb);
        bulk_g2s(d + 3 * ASTRIP, Bb + (size_t)(16 + s) * ASTRIP, 10240, mb);
    };

    if (tid == 0) issue(0, 0);
    for (int s = 0; s < 16; ++s) {
        int buf = s & 1, par = (s >> 1) & 1;
        if (tid == 0 && s + 1 < 16) issue(s + 1, buf ^ 1);
        mbar_wait(&mbar[buf], par);
        const __nv_bfloat16* A0 = sm + buf * (4 * ASTRIP);
        const __nv_bfloat16* A1 = A0 + ASTRIP;
        const __nv_bfloat16* B0 = A0 + 2 * ASTRIP;
        const __nv_bfloat16* B1 = A0 + 3 * ASTRIP;
#pragma unroll
        for (int kk = 0; kk < 2; ++kk) {
            int k16 = kk * 16;
            uint32_t ah[2][4], al[2][4];
#pragma unroll
            for (int im = 0; im < 2; ++im) {
                int aoff = (wm * 32 + im * 16 + (lane & 15)) * 40 + k16 + ((lane >> 4) << 3);
                ldsm4(ah[im], cvta_s(A0 + aoff));
                ldsm4(al[im], cvta_s(A1 + aoff));
            }
            uint32_t bh[4][4], bl[4][4];
#pragma unroll
            for (int h = 0; h < 4; ++h) {
                int boff = (wn * 64 + h * 16 + ((lane >> 4) << 3) + (lane & 7)) * 40
                           + k16 + (((lane >> 3) & 1) << 3);
                ldsm4(bh[h], cvta_s(B0 + boff));
                ldsm4(bl[h], cvta_s(B1 + boff));
            }
#pragma unroll
            for (int im = 0; im < 2; ++im)
#pragma unroll
                for (int nt = 0; nt < 8; ++nt) {
                    uint32_t h0r = bh[nt >> 1][(nt & 1) * 2], h1r = bh[nt >> 1][(nt & 1) * 2 + 1];
                    uint32_t l0r = bl[nt >> 1][(nt & 1) * 2], l1r = bl[nt >> 1][(nt & 1) * 2 + 1];
                    mma_bf16(c[im][nt], ah[im], h0r, h1r);
                    mma_bf16(c[im][nt], ah[im], l0r, l1r);
                    mma_bf16(c[im][nt], al[im], h0r, h1r);
                }
        }
        __syncthreads();
    }
    // epilogue: + bias, write fp32 to blocked layout [t][nb][b][32]
    int gid = lane >> 2, tg = lane & 3;
#pragma unroll
    for (int im = 0; im < 2; ++im) {
        int rb0 = mt0 + wm * 32 + im * 16 + gid;
#pragma unroll
        for (int nt = 0; nt < 8; ++nt) {
            int col = nt0 + wn * 64 + nt * 8 + tg * 2;
            float b0 = __ldg(&g_bias[col]), b1 = __ldg(&g_bias[col + 1]);
            int nbt = col >> 5, cc = col & 31;
#pragma unroll
            for (int rr = 0; rr < 2; ++rr) {
                int m = rb0 + rr * 8;
                float* o = g_xproj +
                    ((((size_t)(m >> 7) * NBLK + nbt) * BATCH + (m & 127)) * 32 + cc);
                o[0] = c[im][nt][rr * 2 + 0] + b0;
                o[1] = c[im][nt][rr * 2 + 1] + b1;
            }
        }
    }
}

// ---------------- persistent LSTM kernel: all 512 steps ---------------------
// smem: W 163840 | A pipe 2x20480 | XP 16384 | C 4096 | mbars
#define SMW_OFF   0
#define SMA_OFF   163840
#define SMXP_OFF  (163840 + 40960)          // 204800
#define SMC_OFF   (SMXP_OFF + 16384)        // 221184
#define SMBAR_OFF (SMC_OFF + 4096)          // 225280
#define PERSIST_SMEM (SMBAR_OFF + 64)       // 225344

__global__ void __launch_bounds__(256) lstm_persist_kernel() {
    extern __shared__ char dyn[];
    __nv_bfloat16* smW = (__nv_bfloat16*)(dyn + SMW_OFF);
    __nv_bfloat16* smA = (__nv_bfloat16*)(dyn + SMA_OFF);
    float* smXP  = (float*)(dyn + SMXP_OFF);
    float* smC   = (float*)(dyn + SMC_OFF);
    float* gates = (float*)(dyn + SMA_OFF);   // alias over A pipe (post-compute)
    uint64_t* mb = (uint64_t*)(dyn + SMBAR_OFF);

    const int tid = threadIdx.x, warp = tid >> 5, lane = tid & 31;
    const int nb = blockIdx.x, n0 = nb * 32, m0 = warp * 16;

    if (tid == 0) {
        mbar_init(&mb[0], 1); mbar_init(&mb[1], 1);
        mbar_init(&mb[2], 1); mbar_init(&mb[3], 1);
        asm volatile("fence.proxy.async.shared::cta;" ::: "memory");
        uint32_t m2 = cvta_s(&mb[2]);
        mbar_expect(m2, 163840);
        bulk_g2s(smW, g_whh2 + (size_t)nb * (64 * BSTRIP), 163840, m2);
    }
    __syncthreads();
    // cell state into smem (block-private: hidden units [nb*8, nb*8+8))
    for (int i = tid; i < 1024; i += 256) {
        int b = i >> 3, jj = i & 7;
        smC[i] = g_c[b * HID + nb * 8 + jj];
    }
    mbar_wait(&mb[2], 0);

    int phA0 = 0, phA1 = 0, phXP = 0;

    for (int t = 0; t < S_LEN; ++t) {
        const __nv_bfloat16* __restrict__ Ab = g_haug2[t & 1];
        __nv_bfloat16* __restrict__ hdst = g_haug2[(t + 1) & 1];

        auto issueA = [&](int s, int buf) {
            uint32_t m = cvta_s(&mb[buf]);
            mbar_expect(m, 20480);
            __nv_bfloat16* d = smA + buf * (2 * ASTRIP);
            bulk_g2s(d,          Ab + (size_t)s * ASTRIP,        10240, m);
            bulk_g2s(d + ASTRIP, Ab + (size_t)(32 + s) * ASTRIP, 10240, m);
        };

        if (tid == 0) {
            uint32_t m3 = cvta_s(&mb[3]);
            mbar_expect(m3, 16384);
            bulk_g2s(smXP, (const char*)g_xproj +
                     (((size_t)t * NBLK + nb) * BATCH * 32) * sizeof(float), 16384, m3);
            issueA(0, 0);
            issueA(1, 1);
        }

        float c4[4][4];
#pragma unroll
        for (int i = 0; i < 4; i++)
#pragma unroll
            for (int j = 0; j < 4; j++) c4[i][j] = 0.f;

        for (int s = 0; s < 32; ++s) {
            int buf = s & 1;
            if (buf == 0) { mbar_wait(&mb[0], phA0); phA0 ^= 1; }
            else          { mbar_wait(&mb[1], phA1); phA1 ^= 1; }
            const __nv_bfloat16* A0 = smA + buf * (2 * ASTRIP);
            const __nv_bfloat16* A1 = A0 + ASTRIP;
            const __nv_bfloat16* B0 = smW + (size_t)s * BSTRIP;
            const __nv_bfloat16* B1 = smW + (size_t)(32 + s) * BSTRIP;
#pragma unroll
            for (int kk = 0; kk < 2; ++kk) {
                int k16 = kk * 16;
                int aoff = (m0 + (lane & 15)) * 40 + k16 + ((lane >> 4) << 3);
                uint32_t ah[4], al[4];
                ldsm4(ah, cvta_s(A0 + aoff));
                ldsm4(al, cvta_s(A1 + aoff));
                uint32_t bh[2][4], bl[2][4];
#pragma unroll
                for (int h = 0; h < 2; ++h) {
                    int boff = (h * 16 + ((lane >> 4) << 3) + (lane & 7)) * 40
                               + k16 + (((lane >> 3) & 1) << 3);
                    ldsm4(bh[h], cvta_s(B0 + boff));
                    ldsm4(bl[h], cvta_s(B1 + boff));
                }
#pragma unroll
                for (int nt = 0; nt < 4; ++nt) {
                    uint32_t h0r = bh[nt >> 1][(nt & 1) * 2], h1r = bh[nt >> 1][(nt & 1) * 2 + 1];
                    uint32_t l0r = bl[nt >> 1][(nt & 1) * 2], l1r = bl[nt >> 1][(nt & 1) * 2 + 1];
                    mma_bf16(c4[nt], ah, h0r, h1r);
                    mma_bf16(c4[nt], ah, l0r, l1r);
                    mma_bf16(c4[nt], al, h0r, h1r);
                }
            }
            __syncthreads();                 // all reads of buf done
            if (tid == 0 && s + 2 < 32) issueA(s + 2, buf);
        }

        // stash recurrent gate pre-activations (aliases A pipe; reads done)
        int gid = lane >> 2, tg = lane & 3;
#pragma unroll
        for (int nt = 0; nt < 4; ++nt) {
            int col = nt * 8 + tg * 2;
            gates[(m0 + gid) * 33 + col]         = c4[nt][0];
            gates[(m0 + gid) * 33 + col + 1]     = c4[nt][1];
            gates[(m0 + gid + 8) * 33 + col]     = c4[nt][2];
            gates[(m0 + gid + 8) * 33 + col + 1] = c4[nt][3];
        }
        __syncthreads();
        mbar_wait(&mb[3], phXP); phXP ^= 1;

        // fused LSTM cell update: 1024 (b, jj) pairs, 4 per thread
#pragma unroll
        for (int i = 0; i < 4; ++i) {
            int p = tid + i * 256;
            int b = p >> 3, jj = p & 7;
            int j = nb * 8 + jj;
            float4 xv = *(const float4*)(smXP + b * 32 + jj * 4);
            float ig = gates[b * 33 + jj * 4 + 0] + xv.x;
            float fg = gates[b * 33 + jj * 4 + 1] + xv.y;
            float gg = gates[b * 33 + jj * 4 + 2] + xv.z;
            float og = gates[b * 33 + jj * 4 + 3] + xv.w;
            float ia = 1.f / (1.f + expf(-ig));
            float fa = 1.f / (1.f + expf(-fg));
            float ga = tanhf(gg);
            float oa = 1.f / (1.f + expf(-og));
            float cn = fa * smC[p] + ia * ga;
            float hn = oa * tanhf(cn);
            smC[p] = cn;
            if (t == S_LEN - 1) g_h[b * HID + j] = hn;
            __nv_bfloat16 hi, lo; bf16_split(hn, hi, lo);
            int sA = j >> 5, kc = j & 31;
            hdst[(size_t)sA * ASTRIP + b * 40 + kc]        = hi;
            hdst[(size_t)(32 + sA) * ASTRIP + b * 40 + kc] = lo;
        }

        if (t + 1 < S_LEN) grid_barrier();
    }
}

// ---------------- decoder + softmax over batch dim -------------------------
__global__ void decoder_kernel(const float* __restrict__ Wdec,
                               const float* __restrict__ bdec,
                               float* __restrict__ out) {
    __shared__ float sl[512];
    __shared__ float red[8];
    int tid = threadIdx.x;
    int b = tid >> 2, o = tid & 3;
    const float4* h4 = (const float4*)(g_h + b * HID);
    const float4* w4 = (const float4*)(Wdec + o * HID);
    float acc = bdec[o];
    for (int k = 0; k < HID / 4; ++k) {
        float4 hv = h4[k], wv = w4[k];
        acc += hv.x * wv.x + hv.y * wv.y + hv.z * wv.z + hv.w * wv.w;
    }
    sl[tid] = acc;
    __syncthreads();
    if (tid < 4) {
        float mx = -1e30f;
        for (int bb = 0; bb < 128; ++bb) mx = fmaxf(mx, sl[bb * 4 + tid]);
        float s = 0.f;
        for (int bb = 0; bb < 128; ++bb) s += expf(sl[bb * 4 + tid] - mx);
        red[tid] = mx; red[4 + tid] = s;
    }
    __syncthreads();
    out[tid] = expf(sl[tid] - red[o]) / red[4 + o];
}

// ---------------- launch ----------------
extern "C" void kernel_launch(void* const* d_in, const int* in_sizes, int n_in,
                              void* d_out, int out_size) {
    const float* inputs = (const float*)d_in[0];
    const float* h0     = (const float*)d_in[1];
    const float* c0     = (const float*)d_in[2];
    const float* Wih    = (const float*)d_in[3];
    const float* Whh    = (const float*)d_in[4];
    const float* bih    = (const float*)d_in[5];
    const float* bhh    = (const float*)d_in[6];
    const float* Wdec   = (const float*)d_in[7];
    const float* bdec   = (const float*)d_in[8];
    float* out = (float*)d_out;

    const int XPROJ_SMEM = 81920 + 32;
    cudaFuncSetAttribute(xproj_kernel, cudaFuncAttributeMaxDynamicSharedMemorySize, XPROJ_SMEM);
    cudaFuncSetAttribute(lstm_persist_kernel, cudaFuncAttributeMaxDynamicSharedMemorySize, PERSIST_SMEM);

    prep_wih_kernel<<<(G4 * INPUT + 255) / 256, 256>>>(Wih);
    prep_whh_kernel<<<(G4 * HID + 255) / 256, 256>>>(Whh);
    prep_bias_kernel<<<(G4 + 255) / 256, 256>>>(bih, bhh);
    prep_x_kernel<<<(int)(((size_t)MX * INPUT + 255) / 256), 256>>>(inputs);
    init_state_kernel<<<(BATCH * HID + 255) / 256, 256>>>(h0, c0);

    xproj_kernel<<<dim3(G4 / 128, MX / 128), 256, XPROJ_SMEM>>>();

    lstm_persist_kernel<<<NBLK, 256, PERSIST_SMEM>>>();

    decoder_kernel<<<1, 512>>>(Wdec, bdec, out);
}

// round 8
// speedup vs baseline: 4.3253x; 1.6759x over previous
#include <cuda_runtime.h>
#include <cuda_fp16.h>
#include <math.h>
#include <stdint.h>

#define S_LEN 512
#define BATCH 128
#define INPUT 512
#define HID   1024
#define G4    4096            // 4*HID, permuted rows: n' = j*4 + gate
#define MX    (S_LEN*BATCH)   // 65536
#define NBLK  128

// K-strips of 32 fp16, padded pitch 40 (80B rows, conflict-free ldmatrix).
// A-strip = 128 rows x 40 = 5120 elems (10240B). B-strip = 32 x 40 (2560B).
#define ASTRIP 5120
#define BSTRIP 1280

// ---------------- device scratch (static, no runtime allocation) ----------
// x image: [mt 512][s 16][128][40] fp16  (mt == timestep t since BATCH=128)
__device__ __half g_xaug2[(size_t)512 * 16 * ASTRIP];     // ~84MB
// W_ih image: [nt 32][s 16][128][40] fp16
__device__ __half g_wih2[(size_t)32 * 16 * ASTRIP];       // ~5.2MB
// W_hh image: [nb 128][s 32][32][40] fp16
__device__ __half g_whh2[(size_t)128 * 32 * BSTRIP];      // ~10.5MB
__device__ float  g_bias[G4];
// x_proj blocked for step prefetch: [t 512][nb 128][b 128][32] fp32 (1GiB)
__device__ float  g_xproj[(size_t)S_LEN * NBLK * BATCH * 32];
__device__ float  g_c[BATCH * HID];
__device__ float  g_h[BATCH * HID];
// recurrent h: [s 32][128 b][40] fp16, ping-pong
__device__ __half g_haug2[2][32 * ASTRIP];
// grid barrier: monotonic counter, reset by init_state_kernel each launch
__device__ unsigned g_cnt;

// ---------------- helpers ----------------
__device__ __forceinline__ uint32_t cvta_s(const void* p) {
    return (uint32_t)__cvta_generic_to_shared(p);
}
__device__ __forceinline__ void ldsm4(uint32_t r[4], uint32_t a) {
    asm volatile("ldmatrix.sync.aligned.m8n8.x4.shared.b16 {%0,%1,%2,%3}, [%4];\n"
                 : "=r"(r[0]), "=r"(r[1]), "=r"(r[2]), "=r"(r[3]) : "r"(a));
}
__device__ __forceinline__ void mma_f16(float* c, const uint32_t* a,
                                        uint32_t b0, uint32_t b1) {
    asm volatile(
        "mma.sync.aligned.m16n8k16.row.col.f32.f16.f16.f32 "
        "{%0,%1,%2,%3},{%4,%5,%6,%7},{%8,%9},{%0,%1,%2,%3};\n"
        : "+f"(c[0]), "+f"(c[1]), "+f"(c[2]), "+f"(c[3])
        : "r"(a[0]), "r"(a[1]), "r"(a[2]), "r"(a[3]), "r"(b0), "r"(b1));
}
__device__ __forceinline__ void mbar_init(void* m, uint32_t cnt) {
    asm volatile("mbarrier.init.shared.b64 [%0], %1;\n"
                 :: "r"(cvta_s(m)), "r"(cnt) : "memory");
}
__device__ __forceinline__ void mbar_expect(uint32_t mb, uint32_t bytes) {
    asm volatile("mbarrier.arrive.expect_tx.shared.b64 _, [%0], %1;\n"
                 :: "r"(mb), "r"(bytes) : "memory");
}
__device__ __forceinline__ void bulk_g2s(void* dst, const void* src,
                                         uint32_t bytes, uint32_t mb) {
    asm volatile("cp.async.bulk.shared::cta.global.mbarrier::complete_tx::bytes "
                 "[%0], [%1], %2, [%3];\n"
                 :: "r"(cvta_s(dst)), "l"(src), "r"(bytes), "r"(mb) : "memory");
}
__device__ __forceinline__ void mbar_wait(void* m, uint32_t parity) {
    uint32_t a = cvta_s(m);
    asm volatile(
        "{\n.reg .pred P;\n"
        "W_%=:\n"
        "mbarrier.try_wait.parity.shared.b64 P, [%0], %1;\n"
        "@!P bra W_%=;\n}\n"
        :: "r"(a), "r"(parity) : "memory");
}

// ---------------- prep kernels ----------------
__global__ void prep_x_kernel(const float* __restrict__ X) {
    size_t idx = (size_t)blockIdx.x * 256 + threadIdx.x;
    if (idx >= (size_t)MX * INPUT) return;
    int m = (int)(idx >> 9), k = (int)(idx & 511);
    int mt = m >> 7, mr = m & 127;
    int s = k >> 5, kc = k & 31;
    g_xaug2[(size_t)(mt * 16 + s) * ASTRIP + mr * 40 + kc] = __float2half(X[idx]);
}
__global__ void prep_wih_kernel(const float* __restrict__ W) {
    int idx = blockIdx.x * 256 + threadIdx.x;
    if (idx >= G4 * INPUT) return;
    int r = idx >> 9, k = idx & 511;
    int g = r >> 10, j = r & 1023;
    int np = j * 4 + g;
    int nt = np >> 7, nr = np & 127;
    int s = k >> 5, kc = k & 31;
    g_wih2[(size_t)(nt * 16 + s) * ASTRIP + nr * 40 + kc] = __float2half(W[idx]);
}
__global__ void prep_whh_kernel(const float* __restrict__ W) {
    int idx = blockIdx.x * 256 + threadIdx.x;
    if (idx >= G4 * HID) return;
    int r = idx >> 10, k = idx & 1023;
    int g = r >> 10, j = r & 1023;
    int np = j * 4 + g;
    int nb = np >> 5, nr = np & 31;
    int s = k >> 5, kc = k & 31;
    g_whh2[(size_t)(nb * 32 + s) * BSTRIP + nr * 40 + kc] = __float2half(W[idx]);
}
__global__ void prep_bias_kernel(const float* __restrict__ bih, const float* __restrict__ bhh) {
    int r = blockIdx.x * 256 + threadIdx.x;
    if (r >= G4) return;
    int g = r >> 10, j = r & 1023;
    g_bias[j * 4 + g] = bih[r] + bhh[r];
}
__global__ void init_state_kernel(const float* __restrict__ h0, const float* __restrict__ c0) {
    int idx = blockIdx.x * 256 + threadIdx.x;
    if (idx == 0) g_cnt = 0u;
    if (idx >= BATCH * HID) return;
    g_c[idx] = c0[idx];
    int b = idx >> 10, j = idx & 1023;
    int s = j >> 5, kc = j & 31;
    g_haug2[0][(size_t)s * ASTRIP + b * 40 + kc] = __float2half(h0[idx]);
}

// ---------------- phase A: x_proj GEMM (M=65536, N=4096, K=512, fp16) ------
// block tile 128x128, 16 K-strip stages, 256 threads (8 warps 4Mx2N).
__global__ void __launch_bounds__(256) xproj_kernel() {
    __shared__ __half As[2][ASTRIP];
    __shared__ __half Bs[2][ASTRIP];
    __shared__ uint64_t mbar[2];

    const int tid = threadIdx.x, warp = tid >> 5, lane = tid & 31;
    const int nt0 = blockIdx.x * 128, mt0 = blockIdx.y * 128;
    const __half* Ab = g_xaug2 + (size_t)blockIdx.y * (16 * ASTRIP);
    const __half* Bb = g_wih2 + (size_t)blockIdx.x * (16 * ASTRIP);
    const int wm = warp >> 1, wn = warp & 1;

    if (tid == 0) {
        mbar_init(&mbar[0], 1); mbar_init(&mbar[1], 1);
        asm volatile("fence.proxy.async.shared::cta;" ::: "memory");
    }
    __syncthreads();

    float c[2][8][4];
#pragma unroll
    for (int i = 0; i < 2; i++)
#pragma unroll
        for (int j = 0; j < 8; j++)
#pragma unroll
            for (int q = 0; q < 4; q++) c[i][j][q] = 0.f;

    auto issue = [&](int s, int buf) {
        uint32_t mb = cvta_s(&mbar[buf]);
        mbar_expect(mb, 20480);
        bulk_g2s(As[buf], Ab + (size_t)s * ASTRIP, 10240, mb);
        bulk_g2s(Bs[buf], Bb + (size_t)s * ASTRIP, 10240, mb);
    };

    if (tid == 0) { issue(0, 0); issue(1, 1); }
    for (int s = 0; s < 16; ++s) {
        int buf = s & 1, par = (s >> 1) & 1;
        mbar_wait(&mbar[buf], par);
#pragma unroll
        for (int kk = 0; kk < 2; ++kk) {
            int k16 = kk * 16;
            uint32_t a[2][4];
#pragma unroll
            for (int im = 0; im < 2; ++im) {
                int aoff = (wm * 32 + im * 16 + (lane & 15)) * 40 + k16 + ((lane >> 4) << 3);
                ldsm4(a[im], cvta_s(&As[buf][aoff]));
            }
            uint32_t b[4][4];
#pragma unroll
            for (int h = 0; h < 4; ++h) {
                int boff = (wn * 64 + h * 16 + ((lane >> 4) << 3) + (lane & 7)) * 40
                           + k16 + (((lane >> 3) & 1) << 3);
                ldsm4(b[h], cvta_s(&Bs[buf][boff]));
            }
#pragma unroll
            for (int im = 0; im < 2; ++im)
#pragma unroll
                for (int nt = 0; nt < 8; ++nt)
                    mma_f16(c[im][nt], a[im], b[nt >> 1][(nt & 1) * 2], b[nt >> 1][(nt & 1) * 2 + 1]);
        }
        __syncthreads();
        if (tid == 0 && s + 2 < 16) issue(s + 2, buf);
    }
    // epilogue: + bias, fp32 blocked store [t][nb][b][32]
    int gid = lane >> 2, tg = lane & 3;
#pragma unroll
    for (int im = 0; im < 2; ++im) {
        int rb0 = mt0 + wm * 32 + im * 16 + gid;
#pragma unroll
        for (int nt = 0; nt < 8; ++nt) {
            int col = nt0 + wn * 64 + nt * 8 + tg * 2;
            float b0 = __ldg(&g_bias[col]), b1 = __ldg(&g_bias[col + 1]);
            int nbt = col >> 5, cc = col & 31;
#pragma unroll
            for (int rr = 0; rr < 2; ++rr) {
                int m = rb0 + rr * 8;
                float* o = g_xproj +
                    ((((size_t)(m >> 7) * NBLK + nbt) * BATCH + (m & 127)) * 32 + cc);
                o[0] = c[im][nt][rr * 2 + 0] + b0;
                o[1] = c[im][nt][rr * 2 + 1] + b1;
            }
        }
    }
}

// ---------------- persistent LSTM kernel: all 512 steps ---------------------
// smem: W 81920 | A ring 8x10240 | XP 16384 | C 4096 | mbars
#define SMW_OFF   0
#define SMA_OFF   81920
#define SMXP_OFF  (81920 + 81920)           // 163840
#define SMC_OFF   (SMXP_OFF + 16384)        // 180224
#define SMBAR_OFF (SMC_OFF + 4096)          // 184320
#define PERSIST_SMEM (SMBAR_OFF + 128)      // 184448

__global__ void __launch_bounds__(256) lstm_persist_kernel() {
    extern __shared__ char dyn[];
    __half* smW = (__half*)(dyn + SMW_OFF);     // [32][1280]
    __half* smA = (__half*)(dyn + SMA_OFF);     // ring [8][5120]
    float* smXP  = (float*)(dyn + SMXP_OFF);
    float* smC   = (float*)(dyn + SMC_OFF);
    float* gates = (float*)(dyn + SMA_OFF);     // alias over A ring (post-compute)
    uint64_t* mb = (uint64_t*)(dyn + SMBAR_OFF); // 0-7 A ring, 8 W, 9 XP

    const int tid = threadIdx.x, warp = tid >> 5, lane = tid & 31;
    const int nb = blockIdx.x, m0 = warp * 16;

    if (tid == 0) {
        for (int i = 0; i < 10; i++) mbar_init(&mb[i], 1);
        asm volatile("fence.proxy.async.shared::cta;" ::: "memory");
        uint32_t mW = cvta_s(&mb[8]);
        mbar_expect(mW, 81920);
        bulk_g2s(smW, g_whh2 + (size_t)nb * (32 * BSTRIP), 81920, mW);
    }
    __syncthreads();
    for (int i = tid; i < 1024; i += 256) {
        int b = i >> 3, jj = i & 7;
        smC[i] = g_c[b * HID + nb * 8 + jj];
    }
    mbar_wait(&mb[8], 0);

    for (int t = 0; t < S_LEN; ++t) {
        const __half* __restrict__ Ab = g_haug2[t & 1];
        __half* __restrict__ hdst = g_haug2[(t + 1) & 1];

        auto issueA = [&](int s) {
            int buf = s & 7;
            uint32_t m = cvta_s(&mb[buf]);
            mbar_expect(m, 10240);
            bulk_g2s(smA + buf * ASTRIP, Ab + (size_t)s * ASTRIP, 10240, m);
        };

        if (tid == 0) {
            uint32_t mXP = cvta_s(&mb[9]);
            mbar_expect(mXP, 16384);
            bulk_g2s(smXP, (const char*)g_xproj +
                     (((size_t)t * NBLK + nb) * BATCH * 32) * sizeof(float), 16384, mXP);
#pragma unroll
            for (int s = 0; s < 8; ++s) issueA(s);
        }

        float c4[4][4];
#pragma unroll
        for (int i = 0; i < 4; i++)
#pragma unroll
            for (int j = 0; j < 4; j++) c4[i][j] = 0.f;

        for (int s = 0; s < 32; ++s) {
            int buf = s & 7;
            int par = (t * 4 + (s >> 3)) & 1;      // buffer use count parity
            mbar_wait(&mb[buf], par);
            const __half* A0 = smA + buf * ASTRIP;
            const __half* B0 = smW + (size_t)s * BSTRIP;
#pragma unroll
            for (int kk = 0; kk < 2; ++kk) {
                int k16 = kk * 16;
                int aoff = (m0 + (lane & 15)) * 40 + k16 + ((lane >> 4) << 3);
                uint32_t a[4];
                ldsm4(a, cvta_s(A0 + aoff));
                uint32_t b[2][4];
#pragma unroll
                for (int h = 0; h < 2; ++h) {
                    int boff = (h * 16 + ((lane >> 4) << 3) + (lane & 7)) * 40
                               + k16 + (((lane >> 3) & 1) << 3);
                    ldsm4(b[h], cvta_s(B0 + boff));
                }
#pragma unroll
                for (int nt = 0; nt < 4; ++nt)
                    mma_f16(c4[nt], a, b[nt >> 1][(nt & 1) * 2], b[nt >> 1][(nt & 1) * 2 + 1]);
            }
            __syncthreads();                 // all reads of buf done
            if (tid == 0 && s + 8 < 32) issueA(s + 8);
        }

        // stash gate pre-activations (aliases A ring; all strips consumed)
        int gid = lane >> 2, tg = lane & 3;
#pragma unroll
        for (int nt = 0; nt < 4; ++nt) {
            int col = nt * 8 + tg * 2;
            gates[(m0 + gid) * 33 + col]         = c4[nt][0];
            gates[(m0 + gid) * 33 + col + 1]     = c4[nt][1];
            gates[(m0 + gid + 8) * 33 + col]     = c4[nt][2];
            gates[(m0 + gid + 8) * 33 + col + 1] = c4[nt][3];
        }
        __syncthreads();
        mbar_wait(&mb[9], t & 1);

        // fused LSTM cell update: 1024 (b, jj) pairs, 4 per thread
#pragma unroll
        for (int i = 0; i < 4; ++i) {
            int p = tid + i * 256;
            int b = p >> 3, jj = p & 7;
            int j = nb * 8 + jj;
            float4 xv = *(const float4*)(smXP + b * 32 + jj * 4);
            float ig = gates[b * 33 + jj * 4 + 0] + xv.x;
            float fg = gates[b * 33 + jj * 4 + 1] + xv.y;
            float gg = gates[b * 33 + jj * 4 + 2] + xv.z;
            float og = gates[b * 33 + jj * 4 + 3] + xv.w;
            float ia = 1.f / (1.f + expf(-ig));
            float fa = 1.f / (1.f + expf(-fg));
            float ga = tanhf(gg);
            float oa = 1.f / (1.f + expf(-og));
            float cn = fa * smC[p] + ia * ga;
            float hn = oa * tanhf(cn);
            smC[p] = cn;
            if (t == S_LEN - 1) g_h[b * HID + j] = hn;
            int sA = j >> 5, kc = j & 31;
            hdst[(size_t)sA * ASTRIP + b * 40 + kc] = __float2half(hn);
        }

        if (t + 1 < S_LEN) {
            // grid barrier: monotonic target (g_cnt reset each launch)
            __threadfence();
            __syncthreads();
            if (tid == 0) {
                unsigned target = (unsigned)(t + 1) * NBLK;
                atomicAdd(&g_cnt, 1u);
                while (*((volatile unsigned*)&g_cnt) < target) __nanosleep(16);
            }
            __syncthreads();
            __threadfence();
        }
    }
}

// ---------------- decoder + softmax over batch dim -------------------------
__global__ void decoder_kernel(const float* __restrict__ Wdec,
                               const float* __restrict__ bdec,
                               float* __restrict__ out) {
    __shared__ float sl[512];
    __shared__ float red[8];
    int tid = threadIdx.x;
    int b = tid >> 2, o = tid & 3;
    const float4* h4 = (const float4*)(g_h + b * HID);
    const float4* w4 = (const float4*)(Wdec + o * HID);
    float acc = bdec[o];
    for (int k = 0; k < HID / 4; ++k) {
        float4 hv = h4[k], wv = w4[k];
        acc += hv.x * wv.x + hv.y * wv.y + hv.z * wv.z + hv.w * wv.w;
    }
    sl[tid] = acc;
    __syncthreads();
    if (tid < 4) {
        float mx = -1e30f;
        for (int bb = 0; bb < 128; ++bb) mx = fmaxf(mx, sl[bb * 4 + tid]);
        float s = 0.f;
        for (int bb = 0; bb < 128; ++bb) s += expf(sl[bb * 4 + tid] - mx);
        red[tid] = mx; red[4 + tid] = s;
    }
    __syncthreads();
    out[tid] = expf(sl[tid] - red[o]) / red[4 + o];
}

// ---------------- launch ----------------
extern "C" void kernel_launch(void* const* d_in, const int* in_sizes, int n_in,
                              void* d_out, int out_size) {
    const float* inputs = (const float*)d_in[0];
    const float* h0     = (const float*)d_in[1];
    const float* c0     = (const float*)d_in[2];
    const float* Wih    = (const float*)d_in[3];
    const float* Whh    = (const float*)d_in[4];
    const float* bih    = (const float*)d_in[5];
    const float* bhh    = (const float*)d_in[6];
    const float* Wdec   = (const float*)d_in[7];
    const float* bdec   = (const float*)d_in[8];
    float* out = (float*)d_out;

    cudaFuncSetAttribute(lstm_persist_kernel, cudaFuncAttributeMaxDynamicSharedMemorySize, PERSIST_SMEM);

    prep_wih_kernel<<<(G4 * INPUT + 255) / 256, 256>>>(Wih);
    prep_whh_kernel<<<(G4 * HID + 255) / 256, 256>>>(Whh);
    prep_bias_kernel<<<(G4 + 255) / 256, 256>>>(bih, bhh);
    prep_x_kernel<<<(int)(((size_t)MX * INPUT + 255) / 256), 256>>>(inputs);
    init_state_kernel<<<(BATCH * HID + 255) / 256, 256>>>(h0, c0);

    xproj_kernel<<<dim3(32, 512), 256>>>();

    lstm_persist_kernel<<<NBLK, 256, PERSIST_SMEM>>>();

    decoder_kernel<<<1, 512>>>(Wdec, bdec, out);
}